// round 6
// baseline (speedup 1.0000x reference)
#include <cuda_runtime.h>
#include <float.h>

#define N_NODES 100000
#define N_EDGES 1200000
#define IN_F 128
#define HID 64
#define OUT_F 40
#define SCAN_B 1024
#define NSCAN ((N_NODES + SCAN_B - 1) / SCAN_B)   // 98 blocks

// ---------------- device scratch (no allocations allowed) ----------------
__device__ int   g_deg[N_NODES];          // in-degree incl. self-loop
__device__ float g_dinv[N_NODES];
__device__ int   g_rowptr[N_NODES + 1];   // CSR row pointers (real edges only)
__device__ int   g_cur[N_NODES];          // fill cursors
__device__ int   g_csr[N_EDGES];          // src node per CSR slot
__device__ int   g_edge[2 * N_EDGES];     // int32 [src | dst]
__device__ int   g_is64;
__device__ int   g_part[NSCAN];           // per-block partial sums
__device__ float g_hs[(size_t)N_NODES * HID];    // dinv-prescaled transformed feats
__device__ float g_h1[(size_t)N_NODES * HID];    // layer-1 activations

// -------- init: detect edge dtype + deg=1 (self-loop) --------
__global__ void k_init(const long long* __restrict__ ei, int n) {
    int i = blockIdx.x * blockDim.x + threadIdx.x;
    if (i < n) g_deg[i] = 1;
    if (i == 0) {
        int ok = 1;
        #pragma unroll
        for (int j = 0; j < 16; j++) {
            long long v = ei[j];
            if (v < 0 || v >= n) ok = 0;
        }
        g_is64 = ok;
    }
}

// convert to int32 + count in-degree of dst half in one pass
__global__ void k_convert(const void* __restrict__ ei, int e) {
    int i = blockIdx.x * blockDim.x + threadIdx.x;
    if (i < 2 * e) {
        int v = g_is64 ? (int)((const long long*)ei)[i]
                       : ((const int*)ei)[i];
        g_edge[i] = v;
        if (i >= e) atomicAdd(&g_deg[v], 1);
    }
}

// -------- scan level A: per-block partial sums (+ dinv) --------
__global__ void __launch_bounds__(SCAN_B) k_scanA(int n) {
    __shared__ int wsum[32];
    int t = threadIdx.x, lane = t & 31, wid = t >> 5;
    int i = blockIdx.x * SCAN_B + t;
    int d = (i < n) ? g_deg[i] : 1;
    if (i < n) g_dinv[i] = rsqrtf((float)d);
    int v = d - 1;
    int s = v;
    #pragma unroll
    for (int o = 16; o > 0; o >>= 1) s += __shfl_xor_sync(0xffffffffu, s, o);
    if (lane == 0) wsum[wid] = s;
    __syncthreads();
    if (wid == 0) {
        int ws = wsum[lane];
        #pragma unroll
        for (int o = 16; o > 0; o >>= 1) ws += __shfl_xor_sync(0xffffffffu, ws, o);
        if (lane == 0) g_part[blockIdx.x] = ws;
    }
}

// -------- scan level B+C fused: each block sums its prefix of partials,
//          then local exclusive scan -> rowptr, cur --------
__global__ void __launch_bounds__(SCAN_B) k_scanC(int n) {
    __shared__ int wsum[32];
    __shared__ int s_off;
    int t = threadIdx.x, lane = t & 31, wid = t >> 5;

    if (wid == 0) {
        int p = 0;
        for (int i = lane; i < (int)blockIdx.x; i += 32) p += g_part[i];
        #pragma unroll
        for (int o = 16; o > 0; o >>= 1) p += __shfl_xor_sync(0xffffffffu, p, o);
        if (lane == 0) {
            s_off = p;
            if (blockIdx.x == NSCAN - 1)
                g_rowptr[n] = p + g_part[NSCAN - 1];  // total real edges
        }
    }

    int i = blockIdx.x * SCAN_B + t;
    int v = (i < n) ? (g_deg[i] - 1) : 0;
    int incl = v;
    #pragma unroll
    for (int o = 1; o < 32; o <<= 1) {
        int u = __shfl_up_sync(0xffffffffu, incl, o);
        if (lane >= o) incl += u;
    }
    if (lane == 31) wsum[wid] = incl;
    __syncthreads();
    if (wid == 0) {
        int ws = wsum[lane];
        int wi = ws;
        #pragma unroll
        for (int o = 1; o < 32; o <<= 1) {
            int u = __shfl_up_sync(0xffffffffu, wi, o);
            if (lane >= o) wi += u;
        }
        wsum[lane] = wi - ws;
    }
    __syncthreads();
    if (i < n) {
        int excl = s_off + wsum[wid] + (incl - v);
        g_rowptr[i] = excl;
        g_cur[i] = excl;
    }
}

__global__ void k_fill(int e) {
    int i = blockIdx.x * blockDim.x + threadIdx.x;
    if (i < e) {
        int s = g_edge[i];
        int d = g_edge[e + i];
        int pos = atomicAdd(&g_cur[d], 1);
        g_csr[pos] = s;
    }
}

// --- dense GEMM: g_hs[n,64] = (A[n,K] @ W[K,64]) * dinv[row] (prescaled) ---
// 64x64 tile per 256-thread block, 4x4 register blocking (proven shape).
template <int K>
__global__ void k_gemm_hs(const float* __restrict__ A, const float* __restrict__ W, int n) {
    __shared__ __align__(16) float sW[64 * 64];
    __shared__ float sA[64 * 65];

    const int t = threadIdx.x;           // 256 threads
    const int row0 = blockIdx.x * 64;
    const int ty = t >> 4, tx = t & 15;  // 16x16 thread tile
    const int r0 = ty * 4, c0 = tx * 4;

    float acc[4][4] = {};

    for (int k0 = 0; k0 < K; k0 += 64) {
        __syncthreads();
        for (int i = t; i < 64 * 64 / 4; i += 256)
            ((float4*)sW)[i] = ((const float4*)(W + (size_t)k0 * 64))[i];
        for (int i = t; i < 64 * 16; i += 256) {
            int r = i >> 4;
            int kc = (i & 15) * 4;
            float4 v = make_float4(0.f, 0.f, 0.f, 0.f);
            if (row0 + r < n)
                v = *(const float4*)(A + (size_t)(row0 + r) * K + k0 + kc);
            float* d = &sA[r * 65 + kc];
            d[0] = v.x; d[1] = v.y; d[2] = v.z; d[3] = v.w;
        }
        __syncthreads();

        #pragma unroll 8
        for (int kk = 0; kk < 64; kk++) {
            float4 w4 = *(float4*)&sW[kk * 64 + c0];
            #pragma unroll
            for (int j = 0; j < 4; j++) {
                float a = sA[(r0 + j) * 65 + kk];
                acc[j][0] += a * w4.x;
                acc[j][1] += a * w4.y;
                acc[j][2] += a * w4.z;
                acc[j][3] += a * w4.w;
            }
        }
    }

    #pragma unroll
    for (int j = 0; j < 4; j++) {
        int r = row0 + r0 + j;
        if (r < n) {
            float dv = g_dinv[r];
            *(float4*)&g_hs[(size_t)r * 64 + c0] =
                make_float4(acc[j][0] * dv, acc[j][1] * dv,
                            acc[j][2] * dv, acc[j][3] * dv);
        }
    }
}

// agg v2: out[v] = act(dinv[v]*(hs[v] + sum_{dst=v} hs[src]) + b)  [hs prescaled]
// TWO warps per node; each warp owns a 32-float half-row (one 128B line per
// gather). Chunk-8 predicated batches: 8 idx loads then 8 independent gathers.
__global__ void k_agg(const float* __restrict__ b, float* __restrict__ out,
                      int n, int do_relu) {
    int gw = (blockIdx.x * blockDim.x + threadIdx.x) >> 5;
    int node = gw >> 1;
    int lane = threadIdx.x & 31;
    if (node >= n) return;
    int f = ((gw & 1) << 5) + lane;   // feature owned by this lane

    int beg = g_rowptr[node], end = g_rowptr[node + 1];
    float a = g_hs[(size_t)node * 64 + f];

    for (int j = beg; j < end; j += 8) {
        int r = end - j;               // >=1
        int s[8];
        float v[8];
        #pragma unroll
        for (int i = 0; i < 8; i++)
            s[i] = (i < r) ? g_csr[j + i] : 0;
        #pragma unroll
        for (int i = 0; i < 8; i++)
            v[i] = (i < r) ? g_hs[(size_t)s[i] * 64 + f] : 0.f;
        a += ((v[0] + v[1]) + (v[2] + v[3])) + ((v[4] + v[5]) + (v[6] + v[7]));
    }

    float vv = a * g_dinv[node] + b[f];
    if (do_relu) vv = fmaxf(vv, 0.f);
    out[(size_t)node * 64 + f] = vv;
}

// ------------- head: logits = emb @ Wc + bc, softmax, argmax -------------
// one warp per node, 16 nodes per 512-thread block.
__global__ void __launch_bounds__(512) k_head(const float* __restrict__ emb,
                       const float* __restrict__ Wc,
                       const float* __restrict__ bc, float* __restrict__ logits,
                       float* __restrict__ soft, float* __restrict__ hard, int n) {
    __shared__ float sW[64 * OUT_F];
    __shared__ float sb[OUT_F];
    __shared__ float sE[16][64];

    int t = threadIdx.x;
    for (int i = t; i < 64 * OUT_F; i += 512) sW[i] = Wc[i];
    if (t < OUT_F) sb[t] = bc[t];

    int w = t >> 5, lane = t & 31;
    int node = blockIdx.x * 16 + w;
    if (node < n) {
        sE[w][lane]      = emb[(size_t)node * 64 + lane];
        sE[w][lane + 32] = emb[(size_t)node * 64 + lane + 32];
    }
    __syncthreads();
    if (node >= n) return;

    float acc0 = sb[lane];
    float acc1 = (lane < 8) ? sb[lane + 32] : 0.f;
    #pragma unroll 8
    for (int k = 0; k < 64; k++) {
        float e = sE[w][k];
        acc0 += e * sW[k * OUT_F + lane];
        if (lane < 8) acc1 += e * sW[k * OUT_F + lane + 32];
    }

    logits[(size_t)node * OUT_F + lane] = acc0;
    if (lane < 8) logits[(size_t)node * OUT_F + lane + 32] = acc1;

    float m = fmaxf(acc0, (lane < 8) ? acc1 : -FLT_MAX);
    #pragma unroll
    for (int o = 16; o > 0; o >>= 1) m = fmaxf(m, __shfl_xor_sync(0xffffffffu, m, o));
    float e0 = __expf(acc0 - m);
    float e1 = (lane < 8) ? __expf(acc1 - m) : 0.f;
    float s = e0 + e1;
    #pragma unroll
    for (int o = 16; o > 0; o >>= 1) s += __shfl_xor_sync(0xffffffffu, s, o);
    float inv = 1.f / s;
    soft[(size_t)node * OUT_F + lane] = e0 * inv;
    if (lane < 8) soft[(size_t)node * OUT_F + lane + 32] = e1 * inv;

    int cand = 0x7fffffff;
    if (acc0 == m) cand = lane;
    if (lane < 8 && acc1 == m) cand = min(cand, lane + 32);
    #pragma unroll
    for (int o = 16; o > 0; o >>= 1) cand = min(cand, __shfl_xor_sync(0xffffffffu, cand, o));
    if (lane == 0) hard[node] = (float)cand;
}

extern "C" void kernel_launch(void* const* d_in, const int* in_sizes, int n_in,
                              void* d_out, int out_size) {
    const float* x  = (const float*)d_in[0];
    const void*  ei = d_in[1];
    const float* W1 = (const float*)d_in[2];
    const float* b1 = (const float*)d_in[3];
    const float* W2 = (const float*)d_in[4];
    const float* b2 = (const float*)d_in[5];
    const float* Wc = (const float*)d_in[6];
    const float* bc = (const float*)d_in[7];

    const int N = in_sizes[0] / IN_F;
    const int E = in_sizes[1] / 2;

    float* outp   = (float*)d_out;
    float* logits = outp;
    float* emb    = outp + (size_t)N * OUT_F;
    float* soft   = emb  + (size_t)N * HID;
    float* hard   = soft + (size_t)N * OUT_F;

    const int TB = 256;

    k_init<<<(N + TB - 1) / TB, TB>>>((const long long*)ei, N);   // 1
    k_convert<<<(2 * E + TB - 1) / TB, TB>>>(ei, E);              // 2
    k_scanA<<<NSCAN, SCAN_B>>>(N);                                // 3 (also dinv)
    k_gemm_hs<IN_F><<<(N + 63) / 64, 256>>>(x, W1, N);            // 4  <- profiled
    k_scanC<<<NSCAN, SCAN_B>>>(N);                                // 5 (B+C fused)
    k_fill<<<(E + TB - 1) / TB, TB>>>(E);                         // 6

    // layer 1 aggregation: g_h1 = relu(agg + b1)
    k_agg<<<((N * 64) + TB - 1) / TB, TB>>>(b1, g_h1, N, 1);      // 7

    // layer 2
    k_gemm_hs<HID><<<(N + 63) / 64, 256>>>(g_h1, W2, N);          // 8
    k_agg<<<((N * 64) + TB - 1) / TB, TB>>>(b2, emb, N, 0);       // 9

    // head
    k_head<<<(N + 15) / 16, 512>>>(emb, Wc, bc, logits, soft, hard, N);  // 10
}

// round 9
// speedup vs baseline: 1.0964x; 1.0964x over previous
#include <cuda_runtime.h>
#include <float.h>

#define N_NODES 100000
#define N_EDGES 1200000
#define IN_F 128
#define HID 64
#define OUT_F 40
#define SCAN_B 1024
#define NSCAN ((N_NODES + SCAN_B - 1) / SCAN_B)   // 98 blocks

// ---------------- device scratch (no allocations allowed) ----------------
__device__ int   g_deg[N_NODES];          // in-degree incl. self-loop
__device__ float g_dinv[N_NODES];
__device__ int   g_rowptr[N_NODES + 1];   // CSR row pointers (real edges only)
__device__ int   g_cur[N_NODES];          // fill cursors
__device__ int   g_csr[N_EDGES];          // src node per CSR slot
__device__ int   g_edge[2 * N_EDGES];     // int32 [src | dst]
__device__ int   g_is64;
__device__ int   g_part[NSCAN];           // per-block partial sums
__device__ float g_hs[(size_t)N_NODES * HID];    // dinv-prescaled transformed feats
__device__ float g_h1[(size_t)N_NODES * HID];    // layer-1 activations

// -------- init: detect edge dtype + deg=1 (self-loop) --------
__global__ void k_init(const long long* __restrict__ ei, int n) {
    int i = blockIdx.x * blockDim.x + threadIdx.x;
    if (i < n) g_deg[i] = 1;
    if (i == 0) {
        int ok = 1;
        #pragma unroll
        for (int j = 0; j < 16; j++) {
            long long v = ei[j];
            if (v < 0 || v >= n) ok = 0;
        }
        g_is64 = ok;
    }
}

// convert to int32 + count in-degree of dst half in one pass
__global__ void k_convert(const void* __restrict__ ei, int e) {
    int i = blockIdx.x * blockDim.x + threadIdx.x;
    if (i < 2 * e) {
        int v = g_is64 ? (int)((const long long*)ei)[i]
                       : ((const int*)ei)[i];
        g_edge[i] = v;
        if (i >= e) atomicAdd(&g_deg[v], 1);
    }
}

// -------- scan level A: per-block partial sums (+ dinv) --------
__global__ void __launch_bounds__(SCAN_B) k_scanA(int n) {
    __shared__ int wsum[32];
    int t = threadIdx.x, lane = t & 31, wid = t >> 5;
    int i = blockIdx.x * SCAN_B + t;
    int d = (i < n) ? g_deg[i] : 1;
    if (i < n) g_dinv[i] = rsqrtf((float)d);
    int v = d - 1;
    int s = v;
    #pragma unroll
    for (int o = 16; o > 0; o >>= 1) s += __shfl_xor_sync(0xffffffffu, s, o);
    if (lane == 0) wsum[wid] = s;
    __syncthreads();
    if (wid == 0) {
        int ws = wsum[lane];
        #pragma unroll
        for (int o = 16; o > 0; o >>= 1) ws += __shfl_xor_sync(0xffffffffu, ws, o);
        if (lane == 0) g_part[blockIdx.x] = ws;
    }
}

// -------- scan level B+C fused: each block sums its prefix of partials,
//          then local exclusive scan -> rowptr, cur --------
__global__ void __launch_bounds__(SCAN_B) k_scanC(int n) {
    __shared__ int wsum[32];
    __shared__ int s_off;
    int t = threadIdx.x, lane = t & 31, wid = t >> 5;

    if (wid == 0) {
        int p = 0;
        for (int i = lane; i < (int)blockIdx.x; i += 32) p += g_part[i];
        #pragma unroll
        for (int o = 16; o > 0; o >>= 1) p += __shfl_xor_sync(0xffffffffu, p, o);
        if (lane == 0) {
            s_off = p;
            if (blockIdx.x == NSCAN - 1)
                g_rowptr[n] = p + g_part[NSCAN - 1];  // total real edges
        }
    }

    int i = blockIdx.x * SCAN_B + t;
    int v = (i < n) ? (g_deg[i] - 1) : 0;
    int incl = v;
    #pragma unroll
    for (int o = 1; o < 32; o <<= 1) {
        int u = __shfl_up_sync(0xffffffffu, incl, o);
        if (lane >= o) incl += u;
    }
    if (lane == 31) wsum[wid] = incl;
    __syncthreads();
    if (wid == 0) {
        int ws = wsum[lane];
        int wi = ws;
        #pragma unroll
        for (int o = 1; o < 32; o <<= 1) {
            int u = __shfl_up_sync(0xffffffffu, wi, o);
            if (lane >= o) wi += u;
        }
        wsum[lane] = wi - ws;
    }
    __syncthreads();
    if (i < n) {
        int excl = s_off + wsum[wid] + (incl - v);
        g_rowptr[i] = excl;
        g_cur[i] = excl;
    }
}

__global__ void k_fill(int e) {
    int i = blockIdx.x * blockDim.x + threadIdx.x;
    if (i < e) {
        int s = g_edge[i];
        int d = g_edge[e + i];
        int pos = atomicAdd(&g_cur[d], 1);
        g_csr[pos] = s;
    }
}

// --- dense GEMM: g_hs[n,64] = (A[n,K] @ W[K,64]) * dinv[row] (prescaled) ---
// 64x64 tile per 256-thread block, 4x4 register blocking (proven shape).
template <int K>
__global__ void k_gemm_hs(const float* __restrict__ A, const float* __restrict__ W, int n) {
    __shared__ __align__(16) float sW[64 * 64];
    __shared__ float sA[64 * 65];

    const int t = threadIdx.x;           // 256 threads
    const int row0 = blockIdx.x * 64;
    const int ty = t >> 4, tx = t & 15;  // 16x16 thread tile
    const int r0 = ty * 4, c0 = tx * 4;

    float acc[4][4] = {};

    for (int k0 = 0; k0 < K; k0 += 64) {
        __syncthreads();
        for (int i = t; i < 64 * 64 / 4; i += 256)
            ((float4*)sW)[i] = ((const float4*)(W + (size_t)k0 * 64))[i];
        for (int i = t; i < 64 * 16; i += 256) {
            int r = i >> 4;
            int kc = (i & 15) * 4;
            float4 v = make_float4(0.f, 0.f, 0.f, 0.f);
            if (row0 + r < n)
                v = *(const float4*)(A + (size_t)(row0 + r) * K + k0 + kc);
            float* d = &sA[r * 65 + kc];
            d[0] = v.x; d[1] = v.y; d[2] = v.z; d[3] = v.w;
        }
        __syncthreads();

        #pragma unroll 8
        for (int kk = 0; kk < 64; kk++) {
            float4 w4 = *(float4*)&sW[kk * 64 + c0];
            #pragma unroll
            for (int j = 0; j < 4; j++) {
                float a = sA[(r0 + j) * 65 + kk];
                acc[j][0] += a * w4.x;
                acc[j][1] += a * w4.y;
                acc[j][2] += a * w4.z;
                acc[j][3] += a * w4.w;
            }
        }
    }

    #pragma unroll
    for (int j = 0; j < 4; j++) {
        int r = row0 + r0 + j;
        if (r < n) {
            float dv = g_dinv[r];
            *(float4*)&g_hs[(size_t)r * 64 + c0] =
                make_float4(acc[j][0] * dv, acc[j][1] * dv,
                            acc[j][2] * dv, acc[j][3] * dv);
        }
    }
}

// agg: out[v] = act(dinv[v]*(hs[v] + sum_{dst=v} hs[src]) + b)  [hs prescaled]
// one warp per node; lane owns float2; broadcast idx loads.
// Batch depth 8 -> 4 -> 1 so up to 8 independent 256B gathers are in flight.
__global__ void k_agg(const float* __restrict__ b, float* __restrict__ out,
                      int n, int do_relu) {
    int gw = (blockIdx.x * blockDim.x + threadIdx.x) >> 5;
    int lane = threadIdx.x & 31;
    if (gw >= n) return;

    int beg = g_rowptr[gw], end = g_rowptr[gw + 1];
    float2 acc = *(const float2*)(g_hs + (size_t)gw * 64 + 2 * lane);
    float ax = acc.x, ay = acc.y;
    float bx = 0.f, by = 0.f;

    int j = beg;
    for (; j + 8 <= end; j += 8) {
        int s0 = g_csr[j];
        int s1 = g_csr[j + 1];
        int s2 = g_csr[j + 2];
        int s3 = g_csr[j + 3];
        int s4 = g_csr[j + 4];
        int s5 = g_csr[j + 5];
        int s6 = g_csr[j + 6];
        int s7 = g_csr[j + 7];
        float2 v0 = *(const float2*)(g_hs + (size_t)s0 * 64 + 2 * lane);
        float2 v1 = *(const float2*)(g_hs + (size_t)s1 * 64 + 2 * lane);
        float2 v2 = *(const float2*)(g_hs + (size_t)s2 * 64 + 2 * lane);
        float2 v3 = *(const float2*)(g_hs + (size_t)s3 * 64 + 2 * lane);
        float2 v4 = *(const float2*)(g_hs + (size_t)s4 * 64 + 2 * lane);
        float2 v5 = *(const float2*)(g_hs + (size_t)s5 * 64 + 2 * lane);
        float2 v6 = *(const float2*)(g_hs + (size_t)s6 * 64 + 2 * lane);
        float2 v7 = *(const float2*)(g_hs + (size_t)s7 * 64 + 2 * lane);
        ax += (v0.x + v1.x) + (v2.x + v3.x);
        bx += (v4.x + v5.x) + (v6.x + v7.x);
        ay += (v0.y + v1.y) + (v2.y + v3.y);
        by += (v4.y + v5.y) + (v6.y + v7.y);
    }
    if (j + 4 <= end) {
        int s0 = g_csr[j];
        int s1 = g_csr[j + 1];
        int s2 = g_csr[j + 2];
        int s3 = g_csr[j + 3];
        float2 v0 = *(const float2*)(g_hs + (size_t)s0 * 64 + 2 * lane);
        float2 v1 = *(const float2*)(g_hs + (size_t)s1 * 64 + 2 * lane);
        float2 v2 = *(const float2*)(g_hs + (size_t)s2 * 64 + 2 * lane);
        float2 v3 = *(const float2*)(g_hs + (size_t)s3 * 64 + 2 * lane);
        ax += (v0.x + v1.x) + (v2.x + v3.x);
        ay += (v0.y + v1.y) + (v2.y + v3.y);
        j += 4;
    }
    for (; j < end; j++) {
        int s = g_csr[j];
        float2 v = *(const float2*)(g_hs + (size_t)s * 64 + 2 * lane);
        bx += v.x;
        by += v.y;
    }
    ax += bx;
    ay += by;

    float dv = g_dinv[gw];
    float vx = ax * dv + b[2 * lane];
    float vy = ay * dv + b[2 * lane + 1];
    if (do_relu) { vx = fmaxf(vx, 0.f); vy = fmaxf(vy, 0.f); }
    *(float2*)(out + (size_t)gw * 64 + 2 * lane) = make_float2(vx, vy);
}

// ------------- head: logits = emb @ Wc + bc, softmax, argmax -------------
// one warp per node, 16 nodes per 512-thread block.
__global__ void __launch_bounds__(512) k_head(const float* __restrict__ emb,
                       const float* __restrict__ Wc,
                       const float* __restrict__ bc, float* __restrict__ logits,
                       float* __restrict__ soft, float* __restrict__ hard, int n) {
    __shared__ float sW[64 * OUT_F];
    __shared__ float sb[OUT_F];
    __shared__ float sE[16][64];

    int t = threadIdx.x;
    for (int i = t; i < 64 * OUT_F; i += 512) sW[i] = Wc[i];
    if (t < OUT_F) sb[t] = bc[t];

    int w = t >> 5, lane = t & 31;
    int node = blockIdx.x * 16 + w;
    if (node < n) {
        sE[w][lane]      = emb[(size_t)node * 64 + lane];
        sE[w][lane + 32] = emb[(size_t)node * 64 + lane + 32];
    }
    __syncthreads();
    if (node >= n) return;

    float acc0 = sb[lane];
    float acc1 = (lane < 8) ? sb[lane + 32] : 0.f;
    #pragma unroll 8
    for (int k = 0; k < 64; k++) {
        float e = sE[w][k];
        acc0 += e * sW[k * OUT_F + lane];
        if (lane < 8) acc1 += e * sW[k * OUT_F + lane + 32];
    }

    logits[(size_t)node * OUT_F + lane] = acc0;
    if (lane < 8) logits[(size_t)node * OUT_F + lane + 32] = acc1;

    float m = fmaxf(acc0, (lane < 8) ? acc1 : -FLT_MAX);
    #pragma unroll
    for (int o = 16; o > 0; o >>= 1) m = fmaxf(m, __shfl_xor_sync(0xffffffffu, m, o));
    float e0 = __expf(acc0 - m);
    float e1 = (lane < 8) ? __expf(acc1 - m) : 0.f;
    float s = e0 + e1;
    #pragma unroll
    for (int o = 16; o > 0; o >>= 1) s += __shfl_xor_sync(0xffffffffu, s, o);
    float inv = 1.f / s;
    soft[(size_t)node * OUT_F + lane] = e0 * inv;
    if (lane < 8) soft[(size_t)node * OUT_F + lane + 32] = e1 * inv;

    int cand = 0x7fffffff;
    if (acc0 == m) cand = lane;
    if (lane < 8 && acc1 == m) cand = min(cand, lane + 32);
    #pragma unroll
    for (int o = 16; o > 0; o >>= 1) cand = min(cand, __shfl_xor_sync(0xffffffffu, cand, o));
    if (lane == 0) hard[node] = (float)cand;
}

extern "C" void kernel_launch(void* const* d_in, const int* in_sizes, int n_in,
                              void* d_out, int out_size) {
    const float* x  = (const float*)d_in[0];
    const void*  ei = d_in[1];
    const float* W1 = (const float*)d_in[2];
    const float* b1 = (const float*)d_in[3];
    const float* W2 = (const float*)d_in[4];
    const float* b2 = (const float*)d_in[5];
    const float* Wc = (const float*)d_in[6];
    const float* bc = (const float*)d_in[7];

    const int N = in_sizes[0] / IN_F;
    const int E = in_sizes[1] / 2;

    float* outp   = (float*)d_out;
    float* logits = outp;
    float* emb    = outp + (size_t)N * OUT_F;
    float* soft   = emb  + (size_t)N * HID;
    float* hard   = soft + (size_t)N * OUT_F;

    const int TB = 256;

    k_init<<<(N + TB - 1) / TB, TB>>>((const long long*)ei, N);   // 1
    k_convert<<<(2 * E + TB - 1) / TB, TB>>>(ei, E);              // 2
    k_scanA<<<NSCAN, SCAN_B>>>(N);                                // 3 (also dinv)
    k_gemm_hs<IN_F><<<(N + 63) / 64, 256>>>(x, W1, N);            // 4  <- profiled
    k_scanC<<<NSCAN, SCAN_B>>>(N);                                // 5 (B+C fused)
    k_fill<<<(E + TB - 1) / TB, TB>>>(E);                         // 6

    // layer 1 aggregation: g_h1 = relu(agg + b1)
    k_agg<<<((N * 32) + TB - 1) / TB, TB>>>(b1, g_h1, N, 1);      // 7

    // layer 2
    k_gemm_hs<HID><<<(N + 63) / 64, 256>>>(g_h1, W2, N);          // 8
    k_agg<<<((N * 32) + TB - 1) / TB, TB>>>(b2, emb, N, 0);       // 9

    // head
    k_head<<<(N + 15) / 16, 512>>>(emb, Wc, bc, logits, soft, hard, N);  // 10
}